// round 1
// baseline (speedup 1.0000x reference)
#include <cuda_runtime.h>

#define RESV 0.16f
#define XMINV (-51.2f)
#define YMINV (-51.2f)
#define EPSV 1e-5f
#define NEGV (-1.0e9f)

// Folded weights (BN fused, layer-1 algebraically collapsed)
__device__ float g_Wx[64], g_Wy[64], g_Wz[64], g_Wr[64];
__device__ float g_Wxc[64], g_Wyc[64], g_Wzm[64], g_b1f[64];
__device__ float g_W2f[64 * 64], g_b2f[64];
__device__ int g_is64;

__global__ void prep_kernel(const float* __restrict__ W1, const float* __restrict__ b1,
                            const float* __restrict__ g1, const float* __restrict__ beta1,
                            const float* __restrict__ m1, const float* __restrict__ v1,
                            const float* __restrict__ W2, const float* __restrict__ b2,
                            const float* __restrict__ g2, const float* __restrict__ beta2,
                            const float* __restrict__ m2, const float* __restrict__ v2,
                            const unsigned* __restrict__ coords_raw, int n_words) {
    int c = threadIdx.x;  // 0..63
    if (c == 0) g_is64 = 1;
    __syncthreads();
    // dtype sniff: int64 storage of small nonneg values => odd 32-bit words all 0
    int nz = 0;
    for (int i = 2 * c + 1; i < n_words; i += 128) nz |= (coords_raw[i] != 0u);
    if (nz) g_is64 = 0;

    float a1 = g1[c] * rsqrtf(v1[c] + EPSV);
    float w0 = W1[0 * 64 + c], w1 = W1[1 * 64 + c], w2 = W1[2 * 64 + c];
    float w3 = W1[3 * 64 + c], w4 = W1[4 * 64 + c], w5 = W1[5 * 64 + c];
    float w6 = W1[6 * 64 + c], w7 = W1[7 * 64 + c], w8 = W1[8 * 64 + c];
    g_Wx[c]  = (w0 + w4 + w7) * a1;   // x: rows 0, 4(xo), 7(xo)
    g_Wy[c]  = (w1 + w5 + w8) * a1;   // y: rows 1, 5(yo), 8(yo)
    g_Wz[c]  = (w2 + w6) * a1;        // z: rows 2, 6(zo)
    g_Wr[c]  = w3 * a1;
    g_Wxc[c] = (w4 + w7) * a1;        // subtract xc * this
    g_Wyc[c] = (w5 + w8) * a1;        // subtract yc * this
    g_Wzm[c] = w6 * a1;               // subtract zmean * this
    g_b1f[c] = (b1[c] - m1[c]) * a1 + beta1[c];

    float a2 = g2[c] * rsqrtf(v2[c] + EPSV);
    for (int k = 0; k < 64; k++) g_W2f[k * 64 + c] = W2[k * 64 + c] * a2;
    g_b2f[c] = (b2[c] - m2[c]) * a2 + beta2[c];
}

__device__ __forceinline__ void fma2(unsigned long long& d, unsigned long long a,
                                     unsigned long long b) {
    asm("fma.rn.f32x2 %0, %1, %2, %0;" : "+l"(d) : "l"(a), "l"(b));
}
__device__ __forceinline__ unsigned long long add2(unsigned long long a, unsigned long long b) {
    unsigned long long r;
    asm("add.rn.f32x2 %0, %1, %2;" : "=l"(r) : "l"(a), "l"(b));
    return r;
}

__global__ void __launch_bounds__(128)
pfn_main(const float4* __restrict__ pillars,
         const void* __restrict__ coords_raw,
         const void* __restrict__ npts_raw,
         float* __restrict__ out, int P) {
    __shared__ float4 s_pts[32];
    __shared__ float s_h1[32 * 64];
    __shared__ float s_zmean;
    __shared__ float s_red[128];

    const int tid = threadIdx.x;
    const int c = tid & 63;      // output channel
    const int half = tid >> 6;   // which half of the points
    const int is64 = g_is64;

    // W2f column c packed into 32 x b64 registers (pairs over k)
    unsigned long long w2[32];
#pragma unroll
    for (int j = 0; j < 32; j++) {
        float lo = g_W2f[(2 * j) * 64 + c];
        float hi = g_W2f[(2 * j + 1) * 64 + c];
        asm("mov.b64 %0, {%1, %2};" : "=l"(w2[j]) : "f"(lo), "f"(hi));
    }
    const float wX = g_Wx[c], wY = g_Wy[c], wZ = g_Wz[c], wR = g_Wr[c];
    const float wXC = g_Wxc[c], wYC = g_Wyc[c], wZM = g_Wzm[c];
    const float b1c = g_b1f[c], b2c = g_b2f[c];

    for (int p = blockIdx.x; p < P; p += gridDim.x) {
        int npts;
        long long ccol, crow;
        if (is64) {
            npts = (int)((const long long*)npts_raw)[p];
            ccol = ((const long long*)coords_raw)[2 * p + 1];
            crow = ((const long long*)coords_raw)[2 * p];
        } else {
            npts = ((const int*)npts_raw)[p];
            ccol = (long long)((const int*)coords_raw)[2 * p + 1];
            crow = (long long)((const int*)coords_raw)[2 * p];
        }
        if (tid < 32 && tid < npts) s_pts[tid] = pillars[(size_t)p * 32 + tid];
        if (tid < 32) {
            float z = (tid < npts) ? s_pts[tid].z : 0.0f;
#pragma unroll
            for (int o = 16; o; o >>= 1) z += __shfl_xor_sync(0xffffffffu, z, o);
            if (tid == 0) s_zmean = z / fmaxf((float)npts, 1.0f);
        }
        __syncthreads();

        const float zmean = s_zmean;
        const float xcv = ((float)ccol + 0.5f) * RESV + XMINV;
        const float ycv = ((float)crow + 0.5f) * RESV + YMINV;
        float Kc = b1c - xcv * wXC;
        Kc -= ycv * wYC;
        Kc -= zmean * wZM;

        // Layer 1: h1[m][c] for valid points only
        for (int m = half; m < npts; m += 2) {
            float4 pt = s_pts[m];
            float h = fmaf(pt.x, wX, Kc);
            h = fmaf(pt.y, wY, h);
            h = fmaf(pt.z, wZ, h);
            h = fmaf(pt.w, wR, h);
            s_h1[m * 64 + c] = fmaxf(h, 0.0f);
        }
        __syncthreads();

        // Layer 2 (packed f32x2 FMA) + running max over valid points
        float best = NEGV;
        for (int m = half; m < npts; m += 2) {
            const float* hrow = s_h1 + m * 64;
            unsigned long long a0 = 0ull, a1 = 0ull, a2 = 0ull, a3 = 0ull;
#pragma unroll
            for (int j = 0; j < 8; j++) {
                ulonglong2 h0 = *(const ulonglong2*)(hrow + j * 8);
                ulonglong2 h1 = *(const ulonglong2*)(hrow + j * 8 + 4);
                fma2(a0, h0.x, w2[j * 4 + 0]);
                fma2(a1, h0.y, w2[j * 4 + 1]);
                fma2(a2, h1.x, w2[j * 4 + 2]);
                fma2(a3, h1.y, w2[j * 4 + 3]);
            }
            unsigned long long s = add2(add2(a0, a1), add2(a2, a3));
            float lo, hi;
            asm("mov.b64 {%0, %1}, %2;" : "=f"(lo), "=f"(hi) : "l"(s));
            float v = lo + hi + b2c;
            v = fmaxf(v, 0.0f);
            best = fmaxf(best, v);
        }
        s_red[tid] = best;
        __syncthreads();
        if (tid < 64) out[(size_t)p * 64 + c] = fmaxf(s_red[c], s_red[64 + c]);
        // next iteration's first __syncthreads() orders s_red/s_h1 reuse
    }
}

extern "C" void kernel_launch(void* const* d_in, const int* in_sizes, int n_in,
                              void* d_out, int out_size) {
    const float* pillars = (const float*)d_in[0];
    const void*  coords  = d_in[1];
    const void*  npts    = d_in[2];
    const float* W1 = (const float*)d_in[3];
    const float* b1 = (const float*)d_in[4];
    const float* g1 = (const float*)d_in[5];
    const float* be1 = (const float*)d_in[6];
    const float* m1 = (const float*)d_in[7];
    const float* v1 = (const float*)d_in[8];
    const float* W2 = (const float*)d_in[9];
    const float* b2 = (const float*)d_in[10];
    const float* g2 = (const float*)d_in[11];
    const float* be2 = (const float*)d_in[12];
    const float* m2 = (const float*)d_in[13];
    const float* v2 = (const float*)d_in[14];

    int P = in_sizes[0] / 128;  // P * M(32) * 4
    int n_words = 2 * P < 4096 ? 2 * P : 4096;  // safe in both dtype cases

    prep_kernel<<<1, 64>>>(W1, b1, g1, be1, m1, v1, W2, b2, g2, be2, m2, v2,
                           (const unsigned*)coords, n_words);

    int grid = 1184;  // ~8 blocks/SM worth of grid-stride work, balanced tail
    if (grid > P) grid = P;
    pfn_main<<<grid, 128>>>((const float4*)pillars, coords, npts, (float*)d_out, P);
}